// round 6
// baseline (speedup 1.0000x reference)
#include <cuda_runtime.h>
#include <cuda_bf16.h>
#include <cstdint>
#include <math.h>

// Problem constants
#define Bz   2
#define Tz   1024
#define Cz   1024
#define Hz   16
#define Lz   8
#define Dz   64
#define HIDz 4096
#define Vz   32000
#define NTOK (Bz * Tz)          // 2048
#define EPSz 1e-5f

// ---------------------------------------------------------------------------
// PTX helpers (base ISA only)
// ---------------------------------------------------------------------------
__device__ __forceinline__ uint32_t smem_u32(const void* p) {
    uint32_t a;
    asm("{ .reg .u64 t; cvta.to.shared.u64 t, %1; cvt.u32.u64 %0, t; }"
        : "=r"(a) : "l"(p));
    return a;
}
__device__ __forceinline__ void ldsm_x4(uint32_t* r, uint32_t addr) {
    asm volatile("ldmatrix.sync.aligned.m8n8.x4.shared.b16 {%0,%1,%2,%3}, [%4];"
        : "=r"(r[0]), "=r"(r[1]), "=r"(r[2]), "=r"(r[3]) : "r"(addr));
}
__device__ __forceinline__ void ldsm_x4t(uint32_t* r, uint32_t addr) {
    asm volatile("ldmatrix.sync.aligned.m8n8.x4.trans.shared.b16 {%0,%1,%2,%3}, [%4];"
        : "=r"(r[0]), "=r"(r[1]), "=r"(r[2]), "=r"(r[3]) : "r"(addr));
}
__device__ __forceinline__ void mma16816(float* d, const uint32_t* a, const uint32_t* b) {
    asm volatile("mma.sync.aligned.m16n8k16.row.col.f32.bf16.bf16.f32 "
        "{%0,%1,%2,%3}, {%4,%5,%6,%7}, {%8,%9}, {%0,%1,%2,%3};"
        : "+f"(d[0]), "+f"(d[1]), "+f"(d[2]), "+f"(d[3])
        : "r"(a[0]), "r"(a[1]), "r"(a[2]), "r"(a[3]), "r"(b[0]), "r"(b[1]));
}
__device__ __forceinline__ void cp16(uint32_t saddr, const void* gaddr) {
    asm volatile("cp.async.ca.shared.global [%0], [%1], 16;"
                 :: "r"(saddr), "l"(gaddr) : "memory");
}
#define CP_COMMIT() asm volatile("cp.async.commit_group;" ::: "memory")
#define CP_WAIT1()  asm volatile("cp.async.wait_group 1;" ::: "memory")
#define CP_WAIT0()  asm volatile("cp.async.wait_group 0;" ::: "memory")

__device__ __forceinline__ uint32_t packbf(float x, float y) {
    __nv_bfloat162 t;
    t.x = __float2bfloat16(x);
    t.y = __float2bfloat16(y);
    return *(uint32_t*)&t;
}

// ---------------------------------------------------------------------------
// Scratch (device globals)
// ---------------------------------------------------------------------------
__device__ float g_x[NTOK * Cz];                    // residual stream (fp32)
__device__ __nv_bfloat16 g_hh  [NTOK * Cz];
__device__ __nv_bfloat16 g_hl  [NTOK * Cz];
__device__ __nv_bfloat16 g_qkvh[NTOK * 3 * Cz];     // qkv (bf16 hi/lo)
__device__ __nv_bfloat16 g_qkvl[NTOK * 3 * Cz];
__device__ __nv_bfloat16 g_atth[NTOK * Cz];
__device__ __nv_bfloat16 g_attl[NTOK * Cz];
__device__ __nv_bfloat16 g_ffnh[NTOK * HIDz];
__device__ __nv_bfloat16 g_ffnl[NTOK * HIDz];

// Pre-transposed + hi/lo-split weights (bf16), [N, K] K-major rows
__device__ __nv_bfloat16 g_qkvT_hi[Lz * 3 * Cz * Cz];
__device__ __nv_bfloat16 g_qkvT_lo[Lz * 3 * Cz * Cz];
__device__ __nv_bfloat16 g_projT_hi[Lz * Cz * Cz];
__device__ __nv_bfloat16 g_projT_lo[Lz * Cz * Cz];
__device__ __nv_bfloat16 g_fc1T_hi[Lz * HIDz * Cz];
__device__ __nv_bfloat16 g_fc1T_lo[Lz * HIDz * Cz];
__device__ __nv_bfloat16 g_fc2T_hi[Lz * Cz * HIDz];
__device__ __nv_bfloat16 g_fc2T_lo[Lz * Cz * HIDz];
__device__ __nv_bfloat16 g_tok_hi[Vz * Cz];
__device__ __nv_bfloat16 g_tok_lo[Vz * Cz];

// ---------------------------------------------------------------------------
// Weight prep
// ---------------------------------------------------------------------------
__global__ void wtrans_kernel(const float* __restrict__ W,
                              __nv_bfloat16* __restrict__ Th,
                              __nv_bfloat16* __restrict__ Tl,
                              int K, int N) {
    __shared__ float t[32][33];
    const float* Wl = W + (size_t)blockIdx.z * K * N;
    __nv_bfloat16* Thl = Th + (size_t)blockIdx.z * K * N;
    __nv_bfloat16* Tll = Tl + (size_t)blockIdx.z * K * N;
    int n0 = blockIdx.x * 32, k0 = blockIdx.y * 32;
    int tx = threadIdx.x, ty = threadIdx.y;
#pragma unroll
    for (int j = 0; j < 32; j += 8)
        t[ty + j][tx] = Wl[(size_t)(k0 + ty + j) * N + n0 + tx];
    __syncthreads();
#pragma unroll
    for (int j = 0; j < 32; j += 8) {
        float v = t[tx][ty + j];
        __nv_bfloat16 h = __float2bfloat16(v);
        float lo = v - __bfloat162float(h);
        size_t o = (size_t)(n0 + ty + j) * K + k0 + tx;
        Thl[o] = h;
        Tll[o] = __float2bfloat16(lo);
    }
}

__global__ void wsplit_kernel(const float* __restrict__ W,
                              __nv_bfloat16* __restrict__ Th,
                              __nv_bfloat16* __restrict__ Tl, int n) {
    int i = blockIdx.x * blockDim.x + threadIdx.x;
    if (i < n) {
        float v = W[i];
        __nv_bfloat16 h = __float2bfloat16(v);
        Th[i] = h;
        Tl[i] = __float2bfloat16(v - __bfloat162float(h));
    }
}

// ---------------------------------------------------------------------------
// mma.sync bf16 GEMM. Block 128x128, 4 warps (64x64 each), BK=64,
// 3-stage cp.async pipeline, hi/lo 3-pass accumulation.
// ---------------------------------------------------------------------------
#define PITCH 144               // 64 bf16 = 128B data + 16B pad (conflict-free)
#define TILE_BYTES (128 * PITCH)          // 18432
#define AH_OFF 0
#define AL_OFF TILE_BYTES
#define BH_OFF (2 * TILE_BYTES)
#define BL_OFF (3 * TILE_BYTES)
#define STG    (4 * TILE_BYTES)           // 73728
#define NSTG   3
#define GSMEM  (NSTG * STG)               // 221184

__global__ __launch_bounds__(128)
void gemm_mma(const __nv_bfloat16* __restrict__ Ah,
              const __nv_bfloat16* __restrict__ Al,
              const __nv_bfloat16* __restrict__ Bh,
              const __nv_bfloat16* __restrict__ Bl,
              float* __restrict__ Cf,
              __nv_bfloat16* __restrict__ Ch,
              __nv_bfloat16* __restrict__ Cl,
              int M, int N, int K,
              const float* __restrict__ bias, const float* __restrict__ res,
              int gelu) {
    extern __shared__ __align__(128) char smem[];
    uint32_t sb = smem_u32(smem);
    int tid = threadIdx.x, wid = tid >> 5, lane = tid & 31;
    int m0 = blockIdx.y * 128, n0 = blockIdx.x * 128;
    int wm = wid & 1, wn = wid >> 1;

    const __nv_bfloat16* Agh = Ah + (size_t)m0 * K;
    const __nv_bfloat16* Agl = Al + (size_t)m0 * K;
    const __nv_bfloat16* Bgh = Bh + (size_t)n0 * K;
    const __nv_bfloat16* Bgl = Bl + (size_t)n0 * K;

    float acc[4][8][4];
#pragma unroll
    for (int i = 0; i < 4; i++)
#pragma unroll
        for (int j = 0; j < 8; j++)
#pragma unroll
            for (int r = 0; r < 4; r++) acc[i][j][r] = 0.f;

    const int NC = K >> 6;

#define ISSUE(c)                                                               \
    {                                                                          \
        uint32_t s0 = sb + ((c) % NSTG) * STG;                                 \
        _Pragma("unroll")                                                      \
        for (int it = 0; it < 8; it++) {                                       \
            int i = it * 128 + tid;                                            \
            int row = i >> 3, seg = i & 7;                                     \
            uint32_t so = row * PITCH + seg * 16;                              \
            size_t go = (size_t)row * K + (size_t)(c) * 64 + seg * 8;          \
            cp16(s0 + AH_OFF + so, Agh + go);                                  \
            cp16(s0 + AL_OFF + so, Agl + go);                                  \
            cp16(s0 + BH_OFF + so, Bgh + go);                                  \
            cp16(s0 + BL_OFF + so, Bgl + go);                                  \
        }                                                                      \
        CP_COMMIT();                                                           \
    }

    ISSUE(0);
    ISSUE(1);

    int r16 = lane & 15, hsel = lane >> 4;
    int bg = lane >> 3;
    int browoff = ((bg & 2) << 2) + (lane & 7);
    int bkoff = (bg & 1) * 8;

    for (int c = 0; c < NC; c++) {
        if (c + 1 < NC) { CP_WAIT1(); } else { CP_WAIT0(); }
        __syncthreads();
        if (c + 2 < NC) ISSUE(c + 2);    // stage (c+2)%3 is free: no conflict
        uint32_t base = sb + (c % NSTG) * STG;
#pragma unroll
        for (int kk = 0; kk < 64; kk += 16) {
            uint32_t ah[16], al[16], bh[16], bl[16];
#pragma unroll
            for (int mt = 0; mt < 4; mt++) {
                uint32_t ad = (uint32_t)((wm * 64 + mt * 16 + r16) * PITCH +
                                         (kk + hsel * 8) * 2);
                ldsm_x4(ah + 4 * mt, base + AH_OFF + ad);
                ldsm_x4(al + 4 * mt, base + AL_OFF + ad);
            }
#pragma unroll
            for (int np = 0; np < 4; np++) {
                uint32_t bd = (uint32_t)((wn * 64 + np * 16 + browoff) * PITCH +
                                         (kk + bkoff) * 2);
                ldsm_x4(bh + 4 * np, base + BH_OFF + bd);
                ldsm_x4(bl + 4 * np, base + BL_OFF + bd);
            }
#pragma unroll
            for (int mt = 0; mt < 4; mt++)
#pragma unroll
                for (int nt = 0; nt < 8; nt++) {
                    uint32_t* bp  = bh + (nt >> 1) * 4 + (nt & 1) * 2;
                    uint32_t* bp2 = bl + (nt >> 1) * 4 + (nt & 1) * 2;
                    mma16816(acc[mt][nt], ah + 4 * mt, bp);
                    mma16816(acc[mt][nt], ah + 4 * mt, bp2);
                    mma16816(acc[mt][nt], al + 4 * mt, bp);
                }
        }
        __syncthreads();
    }
#undef ISSUE

    int gid = lane >> 2, qid = lane & 3;
#pragma unroll
    for (int mt = 0; mt < 4; mt++) {
#pragma unroll
        for (int nt = 0; nt < 8; nt++) {
            int n = n0 + wn * 64 + nt * 8 + 2 * qid;
            float bsum0 = bias ? bias[n] : 0.f;
            float bsum1 = bias ? bias[n + 1] : 0.f;
#pragma unroll
            for (int half = 0; half < 2; half++) {
                int m = m0 + wm * 64 + mt * 16 + gid + half * 8;
                float v0 = acc[mt][nt][half * 2 + 0] + bsum0;
                float v1 = acc[mt][nt][half * 2 + 1] + bsum1;
                if (gelu) {
                    v0 = 0.5f * v0 * (1.f + erff(v0 * 0.70710678118654752f));
                    v1 = 0.5f * v1 * (1.f + erff(v1 * 0.70710678118654752f));
                }
                if (res) {
                    const float* rr = res + (size_t)m * N + n;
                    v0 += rr[0];
                    v1 += rr[1];
                }
                if (Cf) {
                    float2 o;
                    o.x = v0; o.y = v1;
                    *(float2*)(Cf + (size_t)m * N + n) = o;
                }
                if (Ch) {
                    __nv_bfloat162 oh, ol;
                    oh.x = __float2bfloat16(v0);
                    oh.y = __float2bfloat16(v1);
                    ol.x = __float2bfloat16(v0 - __bfloat162float(oh.x));
                    ol.y = __float2bfloat16(v1 - __bfloat162float(oh.y));
                    *(__nv_bfloat162*)(Ch + (size_t)m * N + n) = oh;
                    *(__nv_bfloat162*)(Cl + (size_t)m * N + n) = ol;
                }
            }
        }
    }
}

// ---------------------------------------------------------------------------
// MMA flash attention (unchanged from R5)
// ---------------------------------------------------------------------------
#define APITCH  144
#define AT_TILE 9216
#define AT_Q    0
#define AT_KV0  (2 * AT_TILE)
#define AT_KVS  (4 * AT_TILE)
#define AT_SMEM (AT_KV0 + 2 * AT_KVS)

__global__ __launch_bounds__(128)
void attn_mma(const __nv_bfloat16* __restrict__ qkvh,
              const __nv_bfloat16* __restrict__ qkvl,
              __nv_bfloat16* __restrict__ oh,
              __nv_bfloat16* __restrict__ ol) {
    extern __shared__ __align__(128) char smem[];
    uint32_t sb = smem_u32(smem);
    int tid = threadIdx.x, w = tid >> 5, lane = tid & 31;
    int qi = (int)gridDim.x - 1 - (int)blockIdx.x;
    int bh = blockIdx.y;
    int b = bh >> 4, h = bh & 15;
    const int RS = 3 * Cz;
    const size_t tokbase = (size_t)(b * Tz) * RS + h * Dz;

    int gid = lane >> 2, qid = lane & 3;
    int r16 = lane & 15, hsel = lane >> 4;
    int bg = lane >> 3;
    int browoff = ((bg & 2) << 2) + (lane & 7);
    int bkoff = (bg & 1) * 8;
    int t_row = (bg & 1) * 8 + (lane & 7);
    int t_col = (bg >> 1) * 8;

#define ISSUE_KV(kt)                                                           \
    {                                                                          \
        uint32_t s0 = sb + AT_KV0 + ((kt) & 1) * AT_KVS;                       \
        const __nv_bfloat16* srcs[4] = {                                       \
            qkvh + tokbase + Cz, qkvl + tokbase + Cz,                          \
            qkvh + tokbase + 2 * Cz, qkvl + tokbase + 2 * Cz };                \
        _Pragma("unroll")                                                      \
        for (int t = 0; t < 4; t++) {                                          \
            _Pragma("unroll")                                                  \
            for (int it = 0; it < 4; it++) {                                   \
                int i = it * 128 + tid;                                        \
                int r = i >> 3, s = i & 7;                                     \
                cp16(s0 + t * AT_TILE + r * APITCH + s * 16,                   \
                     srcs[t] + (size_t)((kt) * 64 + r) * RS + s * 8);          \
            }                                                                  \
        }                                                                      \
        CP_COMMIT();                                                           \
    }

    {
#pragma unroll
        for (int t = 0; t < 2; t++) {
            const __nv_bfloat16* src = (t ? qkvl : qkvh) + tokbase;
            uint32_t dst = sb + AT_Q + t * AT_TILE;
#pragma unroll
            for (int it = 0; it < 4; it++) {
                int i = it * 128 + tid;
                int r = i >> 3, s = i & 7;
                cp16(dst + r * APITCH + s * 16,
                     src + (size_t)(qi * 64 + r) * RS + s * 8);
            }
        }
        uint32_t s0 = sb + AT_KV0;
        const __nv_bfloat16* srcs[4] = {
            qkvh + tokbase + Cz, qkvl + tokbase + Cz,
            qkvh + tokbase + 2 * Cz, qkvl + tokbase + 2 * Cz };
#pragma unroll
        for (int t = 0; t < 4; t++) {
#pragma unroll
            for (int it = 0; it < 4; it++) {
                int i = it * 128 + tid;
                int r = i >> 3, s = i & 7;
                cp16(s0 + t * AT_TILE + r * APITCH + s * 16,
                     srcs[t] + (size_t)r * RS + s * 8);
            }
        }
        CP_COMMIT();
    }
    if (qi >= 1) ISSUE_KV(1);

    if (qi >= 1) { CP_WAIT1(); } else { CP_WAIT0(); }
    __syncthreads();

    uint32_t qfh[4][4], qfl[4][4];
#pragma unroll
    for (int kk = 0; kk < 4; kk++) {
        uint32_t ad = sb + AT_Q + (uint32_t)((w * 16 + r16) * APITCH +
                                             (kk * 16 + hsel * 8) * 2);
        ldsm_x4(qfh[kk], ad);
        ldsm_x4(qfl[kk], ad + AT_TILE);
    }

    float oacc[8][4];
#pragma unroll
    for (int i = 0; i < 8; i++)
#pragma unroll
        for (int j = 0; j < 4; j++) oacc[i][j] = 0.f;
    float mrow[2] = {-1e30f, -1e30f};
    float lrow[2] = {0.f, 0.f};

    for (int kt = 0; kt <= qi; kt++) {
        if (kt > 0) {
            if (kt < qi) { CP_WAIT1(); } else { CP_WAIT0(); }
            __syncthreads();
        }
        uint32_t kb = sb + AT_KV0 + (kt & 1) * AT_KVS;

        float s[8][4];
#pragma unroll
        for (int i = 0; i < 8; i++)
#pragma unroll
            for (int j = 0; j < 4; j++) s[i][j] = 0.f;
#pragma unroll
        for (int kk = 0; kk < 4; kk++) {
            uint32_t kh[16], kl[16];
#pragma unroll
            for (int np = 0; np < 4; np++) {
                uint32_t ad = kb + (uint32_t)((np * 16 + browoff) * APITCH +
                                              (kk * 16 + bkoff) * 2);
                ldsm_x4(kh + 4 * np, ad);
                ldsm_x4(kl + 4 * np, ad + AT_TILE);
            }
#pragma unroll
            for (int nt = 0; nt < 8; nt++) {
                uint32_t* bp = kh + (nt >> 1) * 4 + (nt & 1) * 2;
                uint32_t* bl2 = kl + (nt >> 1) * 4 + (nt & 1) * 2;
                mma16816(s[nt], qfh[kk], bp);
                mma16816(s[nt], qfh[kk], bl2);
                mma16816(s[nt], qfl[kk], bp);
            }
        }
#pragma unroll
        for (int nt = 0; nt < 8; nt++)
#pragma unroll
            for (int j = 0; j < 4; j++) s[nt][j] *= 0.125f;
        if (kt == qi) {
#pragma unroll
            for (int nt = 0; nt < 8; nt++)
#pragma unroll
                for (int j = 0; j < 4; j++) {
                    int kc = 8 * nt + 2 * qid + (j & 1);
                    int qr = w * 16 + gid + (j >> 1) * 8;
                    if (kc > qr) s[nt][j] = -1e30f;
                }
        }
        float mt0 = -1e30f, mt1 = -1e30f;
#pragma unroll
        for (int nt = 0; nt < 8; nt++) {
            mt0 = fmaxf(mt0, fmaxf(s[nt][0], s[nt][1]));
            mt1 = fmaxf(mt1, fmaxf(s[nt][2], s[nt][3]));
        }
        mt0 = fmaxf(mt0, __shfl_xor_sync(0xffffffffu, mt0, 1));
        mt0 = fmaxf(mt0, __shfl_xor_sync(0xffffffffu, mt0, 2));
        mt1 = fmaxf(mt1, __shfl_xor_sync(0xffffffffu, mt1, 1));
        mt1 = fmaxf(mt1, __shfl_xor_sync(0xffffffffu, mt1, 2));
        float mn0 = fmaxf(mrow[0], mt0), mn1 = fmaxf(mrow[1], mt1);
        float c0 = __expf(mrow[0] - mn0), c1 = __expf(mrow[1] - mn1);
        mrow[0] = mn0; mrow[1] = mn1;
        float rs0 = 0.f, rs1 = 0.f;
#pragma unroll
        for (int nt = 0; nt < 8; nt++) {
            s[nt][0] = __expf(s[nt][0] - mn0);
            s[nt][1] = __expf(s[nt][1] - mn0);
            s[nt][2] = __expf(s[nt][2] - mn1);
            s[nt][3] = __expf(s[nt][3] - mn1);
            rs0 += s[nt][0] + s[nt][1];
            rs1 += s[nt][2] + s[nt][3];
        }
        rs0 += __shfl_xor_sync(0xffffffffu, rs0, 1);
        rs0 += __shfl_xor_sync(0xffffffffu, rs0, 2);
        rs1 += __shfl_xor_sync(0xffffffffu, rs1, 1);
        rs1 += __shfl_xor_sync(0xffffffffu, rs1, 2);
        lrow[0] = lrow[0] * c0 + rs0;
        lrow[1] = lrow[1] * c1 + rs1;
#pragma unroll
        for (int nt = 0; nt < 8; nt++) {
            oacc[nt][0] *= c0; oacc[nt][1] *= c0;
            oacc[nt][2] *= c1; oacc[nt][3] *= c1;
        }
#pragma unroll
        for (int k2 = 0; k2 < 4; k2++) {
            uint32_t pah[4], pal[4];
            {
                float p00 = s[2 * k2][0],     p01 = s[2 * k2][1];
                float p10 = s[2 * k2][2],     p11 = s[2 * k2][3];
                float p20 = s[2 * k2 + 1][0], p21 = s[2 * k2 + 1][1];
                float p30 = s[2 * k2 + 1][2], p31 = s[2 * k2 + 1][3];
                pah[0] = packbf(p00, p01);
                pah[1] = packbf(p10, p11);
                pah[2] = packbf(p20, p21);
                pah[3] = packbf(p30, p31);
                __nv_bfloat162* hp;
                hp = (__nv_bfloat162*)&pah[0];
                pal[0] = packbf(p00 - __bfloat162float(hp->x), p01 - __bfloat162float(hp->y));
                hp = (__nv_bfloat162*)&pah[1];
                pal[1] = packbf(p10 - __bfloat162float(hp->x), p11 - __bfloat162float(hp->y));
                hp = (__nv_bfloat162*)&pah[2];
                pal[2] = packbf(p20 - __bfloat162float(hp->x), p21 - __bfloat162float(hp->y));
                hp = (__nv_bfloat162*)&pah[3];
                pal[3] = packbf(p30 - __bfloat162float(hp->x), p31 - __bfloat162float(hp->y));
            }
            uint32_t vh[16], vl[16];
#pragma unroll
            for (int np = 0; np < 4; np++) {
                uint32_t ad = kb + 2 * AT_TILE +
                              (uint32_t)((k2 * 16 + t_row) * APITCH +
                                         (np * 16 + t_col) * 2);
                ldsm_x4t(vh + 4 * np, ad);
                ldsm_x4t(vl + 4 * np, ad + AT_TILE);
            }
#pragma unroll
            for (int nt = 0; nt < 8; nt++) {
                uint32_t* bp = vh + (nt >> 1) * 4 + (nt & 1) * 2;
                uint32_t* bl2 = vl + (nt >> 1) * 4 + (nt & 1) * 2;
                mma16816(oacc[nt], pah, bp);
                mma16816(oacc[nt], pah, bl2);
                mma16816(oacc[nt], pal, bp);
            }
        }
        __syncthreads();
        if (kt + 2 <= qi) ISSUE_KV(kt + 2);
    }
#undef ISSUE_KV

    float inv0 = 1.f / lrow[0], inv1 = 1.f / lrow[1];
    int tok0 = b * Tz + qi * 64 + w * 16 + gid;
#pragma unroll
    for (int nt = 0; nt < 8; nt++) {
        int col = h * Dz + 8 * nt + 2 * qid;
        float v0 = oacc[nt][0] * inv0, v1 = oacc[nt][1] * inv0;
        float v2 = oacc[nt][2] * inv1, v3 = oacc[nt][3] * inv1;
        __nv_bfloat162 ph, pl;
        ph.x = __float2bfloat16(v0); ph.y = __float2bfloat16(v1);
        pl.x = __float2bfloat16(v0 - __bfloat162float(ph.x));
        pl.y = __float2bfloat16(v1 - __bfloat162float(ph.y));
        *(__nv_bfloat162*)(oh + (size_t)tok0 * Cz + col) = ph;
        *(__nv_bfloat162*)(ol + (size_t)tok0 * Cz + col) = pl;
        ph.x = __float2bfloat16(v2); ph.y = __float2bfloat16(v3);
        pl.x = __float2bfloat16(v2 - __bfloat162float(ph.x));
        pl.y = __float2bfloat16(v3 - __bfloat162float(ph.y));
        *(__nv_bfloat162*)(oh + (size_t)(tok0 + 8) * Cz + col) = ph;
        *(__nv_bfloat162*)(ol + (size_t)(tok0 + 8) * Cz + col) = pl;
    }
}

// ---------------------------------------------------------------------------
// Embedding
// ---------------------------------------------------------------------------
__global__ void embed_kernel(const int* __restrict__ idx,
                             const float* __restrict__ tok,
                             const float* __restrict__ pos,
                             float* __restrict__ x) {
    int row = blockIdx.x;
    int t   = row & (Tz - 1);
    int tokid = idx[row];
    const float* te = tok + (size_t)tokid * Cz;
    const float* pe = pos + (size_t)t * Cz;
    float* xr = x + (size_t)row * Cz;
    for (int i = threadIdx.x; i < Cz; i += blockDim.x)
        xr[i] = te[i] + pe[i];
}

// ---------------------------------------------------------------------------
// LayerNorm per row, writes bf16 hi/lo split
// ---------------------------------------------------------------------------
__global__ void ln_kernel(const float* __restrict__ x,
                          __nv_bfloat16* __restrict__ yh,
                          __nv_bfloat16* __restrict__ yl,
                          const float* __restrict__ g, const float* __restrict__ b) {
    int row = blockIdx.x;
    const float* xr = x + (size_t)row * Cz;
    float s = 0.f, s2 = 0.f;
    for (int i = threadIdx.x; i < Cz; i += blockDim.x) {
        float v = xr[i];
        s += v; s2 += v * v;
    }
    __shared__ float sh_s[8], sh_s2[8];
    for (int off = 16; off > 0; off >>= 1) {
        s  += __shfl_down_sync(0xffffffffu, s,  off);
        s2 += __shfl_down_sync(0xffffffffu, s2, off);
    }
    int lane = threadIdx.x & 31, wid = threadIdx.x >> 5;
    if (lane == 0) { sh_s[wid] = s; sh_s2[wid] = s2; }
    __syncthreads();
    if (wid == 0) {
        s  = (lane < 8) ? sh_s[lane]  : 0.f;
        s2 = (lane < 8) ? sh_s2[lane] : 0.f;
        for (int off = 4; off > 0; off >>= 1) {
            s  += __shfl_down_sync(0xffffffffu, s,  off);
            s2 += __shfl_down_sync(0xffffffffu, s2, off);
        }
        if (lane == 0) { sh_s[0] = s; sh_s2[0] = s2; }
    }
    __syncthreads();
    float mean = sh_s[0] * (1.f / Cz);
    float var  = sh_s2[0] * (1.f / Cz) - mean * mean;
    float rstd = rsqrtf(var + EPSz);
    __nv_bfloat16* yhr = yh + (size_t)row * Cz;
    __nv_bfloat16* ylr = yl + (size_t)row * Cz;
    for (int i = threadIdx.x; i < Cz; i += blockDim.x) {
        float v = (xr[i] - mean) * rstd * g[i] + b[i];
        __nv_bfloat16 h = __float2bfloat16(v);
        yhr[i] = h;
        ylr[i] = __float2bfloat16(v - __bfloat162float(h));
    }
}

// ---------------------------------------------------------------------------
// Launch
// ---------------------------------------------------------------------------
extern "C" void kernel_launch(void* const* d_in, const int* in_sizes, int n_in,
                              void* d_out, int out_size) {
    const int*   idx     = (const int*)  d_in[0];
    const float* tok_emb = (const float*)d_in[1];
    const float* pos_emb = (const float*)d_in[2];
    const float* qkv_w   = (const float*)d_in[3];
    const float* proj_w  = (const float*)d_in[4];
    const float* proj_b  = (const float*)d_in[5];
    const float* ln1_g   = (const float*)d_in[6];
    const float* ln1_b   = (const float*)d_in[7];
    const float* ln2_g   = (const float*)d_in[8];
    const float* ln2_b   = (const float*)d_in[9];
    const float* fc1_w   = (const float*)d_in[10];
    const float* fc1_b   = (const float*)d_in[11];
    const float* fc2_w   = (const float*)d_in[12];
    const float* fc2_b   = (const float*)d_in[13];
    const float* lnf_g   = (const float*)d_in[14];
    const float* lnf_b   = (const float*)d_in[15];
    float* out = (float*)d_out;

    float* x;
    cudaGetSymbolAddress((void**)&x, g_x);
    __nv_bfloat16 *hh, *hl, *qkvh, *qkvl, *atth, *attl, *ffnh, *ffnl;
    cudaGetSymbolAddress((void**)&hh,   g_hh);
    cudaGetSymbolAddress((void**)&hl,   g_hl);
    cudaGetSymbolAddress((void**)&qkvh, g_qkvh);
    cudaGetSymbolAddress((void**)&qkvl, g_qkvl);
    cudaGetSymbolAddress((void**)&atth, g_atth);
    cudaGetSymbolAddress((void**)&attl, g_attl);
    cudaGetSymbolAddress((void**)&ffnh, g_ffnh);
    cudaGetSymbolAddress((void**)&ffnl, g_ffnl);
    __nv_bfloat16 *qkvTh, *qkvTl, *projTh, *projTl, *fc1Th, *fc1Tl, *fc2Th, *fc2Tl, *tokh, *tokl;
    cudaGetSymbolAddress((void**)&qkvTh, g_qkvT_hi);
    cudaGetSymbolAddress((void**)&qkvTl, g_qkvT_lo);
    cudaGetSymbolAddress((void**)&projTh, g_projT_hi);
    cudaGetSymbolAddress((void**)&projTl, g_projT_lo);
    cudaGetSymbolAddress((void**)&fc1Th, g_fc1T_hi);
    cudaGetSymbolAddress((void**)&fc1Tl, g_fc1T_lo);
    cudaGetSymbolAddress((void**)&fc2Th, g_fc2T_hi);
    cudaGetSymbolAddress((void**)&fc2Tl, g_fc2T_lo);
    cudaGetSymbolAddress((void**)&tokh, g_tok_hi);
    cudaGetSymbolAddress((void**)&tokl, g_tok_lo);

    cudaFuncSetAttribute(gemm_mma, cudaFuncAttributeMaxDynamicSharedMemorySize, GSMEM);
    cudaFuncSetAttribute(attn_mma, cudaFuncAttributeMaxDynamicSharedMemorySize, AT_SMEM);

    // ---- weight prep ----
    dim3 tb(32, 8);
    wtrans_kernel<<<dim3(3 * Cz / 32, Cz / 32, Lz), tb>>>(qkv_w, qkvTh, qkvTl, Cz, 3 * Cz);
    wtrans_kernel<<<dim3(Cz / 32, Cz / 32, Lz), tb>>>(proj_w, projTh, projTl, Cz, Cz);
    wtrans_kernel<<<dim3(HIDz / 32, Cz / 32, Lz), tb>>>(fc1_w, fc1Th, fc1Tl, Cz, HIDz);
    wtrans_kernel<<<dim3(Cz / 32, HIDz / 32, Lz), tb>>>(fc2_w, fc2Th, fc2Tl, HIDz, Cz);
    wsplit_kernel<<<(Vz * Cz + 255) / 256, 256>>>(tok_emb, tokh, tokl, Vz * Cz);

    embed_kernel<<<NTOK, 256>>>(idx, tok_emb, pos_emb, x);

    for (int l = 0; l < Lz; l++) {
        const __nv_bfloat16* qwh = qkvTh + (size_t)l * 3 * Cz * Cz;
        const __nv_bfloat16* qwl = qkvTl + (size_t)l * 3 * Cz * Cz;
        const __nv_bfloat16* pwh = projTh + (size_t)l * Cz * Cz;
        const __nv_bfloat16* pwl = projTl + (size_t)l * Cz * Cz;
        const __nv_bfloat16* w1h = fc1Th + (size_t)l * Cz * HIDz;
        const __nv_bfloat16* w1l = fc1Tl + (size_t)l * Cz * HIDz;
        const __nv_bfloat16* w2h = fc2Th + (size_t)l * Cz * HIDz;
        const __nv_bfloat16* w2l = fc2Tl + (size_t)l * Cz * HIDz;
        const float* pb  = proj_b + (size_t)l * Cz;
        const float* b1  = fc1_b  + (size_t)l * HIDz;
        const float* b2  = fc2_b  + (size_t)l * Cz;

        ln_kernel<<<NTOK, 256>>>(x, hh, hl, ln1_g + l * Cz, ln1_b + l * Cz);
        gemm_mma<<<dim3(3 * Cz / 128, NTOK / 128), 128, GSMEM>>>(
            hh, hl, qwh, qwl, nullptr, qkvh, qkvl,
            NTOK, 3 * Cz, Cz, nullptr, nullptr, 0);
        attn_mma<<<dim3(Tz / 64, Bz * Hz), 128, AT_SMEM>>>(qkvh, qkvl, atth, attl);
        gemm_mma<<<dim3(Cz / 128, NTOK / 128), 128, GSMEM>>>(
            atth, attl, pwh, pwl, x, nullptr, nullptr,
            NTOK, Cz, Cz, pb, x, 0);
        ln_kernel<<<NTOK, 256>>>(x, hh, hl, ln2_g + l * Cz, ln2_b + l * Cz);
        gemm_mma<<<dim3(HIDz / 128, NTOK / 128), 128, GSMEM>>>(
            hh, hl, w1h, w1l, nullptr, ffnh, ffnl,
            NTOK, HIDz, Cz, b1, nullptr, 1);
        gemm_mma<<<dim3(Cz / 128, NTOK / 128), 128, GSMEM>>>(
            ffnh, ffnl, w2h, w2l, x, nullptr, nullptr,
            NTOK, Cz, HIDz, b2, x, 0);
    }

    ln_kernel<<<NTOK, 256>>>(x, hh, hl, lnf_g, lnf_b);
    gemm_mma<<<dim3(Vz / 128, NTOK / 128), 128, GSMEM>>>(
        hh, hl, tokh, tokl, out, nullptr, nullptr,
        NTOK, Vz, Cz, nullptr, nullptr, 0);
}

// round 7
// speedup vs baseline: 1.0650x; 1.0650x over previous
#include <cuda_runtime.h>
#include <cuda_bf16.h>
#include <cstdint>
#include <math.h>

// Problem constants
#define Bz   2
#define Tz   1024
#define Cz   1024
#define Hz   16
#define Lz   8
#define Dz   64
#define HIDz 4096
#define Vz   32000
#define NTOK (Bz * Tz)          // 2048
#define EPSz 1e-5f

// ---------------------------------------------------------------------------
// PTX helpers (base ISA only)
// ---------------------------------------------------------------------------
__device__ __forceinline__ uint32_t smem_u32(const void* p) {
    uint32_t a;
    asm("{ .reg .u64 t; cvta.to.shared.u64 t, %1; cvt.u32.u64 %0, t; }"
        : "=r"(a) : "l"(p));
    return a;
}
__device__ __forceinline__ void ldsm_x4(uint32_t* r, uint32_t addr) {
    asm volatile("ldmatrix.sync.aligned.m8n8.x4.shared.b16 {%0,%1,%2,%3}, [%4];"
        : "=r"(r[0]), "=r"(r[1]), "=r"(r[2]), "=r"(r[3]) : "r"(addr));
}
__device__ __forceinline__ void ldsm_x4t(uint32_t* r, uint32_t addr) {
    asm volatile("ldmatrix.sync.aligned.m8n8.x4.trans.shared.b16 {%0,%1,%2,%3}, [%4];"
        : "=r"(r[0]), "=r"(r[1]), "=r"(r[2]), "=r"(r[3]) : "r"(addr));
}
__device__ __forceinline__ void mma16816(float* d, const uint32_t* a, const uint32_t* b) {
    asm volatile("mma.sync.aligned.m16n8k16.row.col.f32.bf16.bf16.f32 "
        "{%0,%1,%2,%3}, {%4,%5,%6,%7}, {%8,%9}, {%0,%1,%2,%3};"
        : "+f"(d[0]), "+f"(d[1]), "+f"(d[2]), "+f"(d[3])
        : "r"(a[0]), "r"(a[1]), "r"(a[2]), "r"(a[3]), "r"(b[0]), "r"(b[1]));
}
__device__ __forceinline__ void cp16(uint32_t saddr, const void* gaddr) {
    asm volatile("cp.async.ca.shared.global [%0], [%1], 16;"
                 :: "r"(saddr), "l"(gaddr) : "memory");
}
#define CP_COMMIT() asm volatile("cp.async.commit_group;" ::: "memory")
#define CP_WAIT1()  asm volatile("cp.async.wait_group 1;" ::: "memory")
#define CP_WAIT0()  asm volatile("cp.async.wait_group 0;" ::: "memory")

__device__ __forceinline__ uint32_t packbf(float x, float y) {
    __nv_bfloat162 t;
    t.x = __float2bfloat16(x);
    t.y = __float2bfloat16(y);
    return *(uint32_t*)&t;
}

// ---------------------------------------------------------------------------
// Scratch (device globals)
// ---------------------------------------------------------------------------
__device__ float g_x[NTOK * Cz];
__device__ __nv_bfloat16 g_hh  [NTOK * Cz];
__device__ __nv_bfloat16 g_hl  [NTOK * Cz];
__device__ __nv_bfloat16 g_qkvh[NTOK * 3 * Cz];
__device__ __nv_bfloat16 g_qkvl[NTOK * 3 * Cz];
__device__ __nv_bfloat16 g_atth[NTOK * Cz];
__device__ __nv_bfloat16 g_attl[NTOK * Cz];
__device__ __nv_bfloat16 g_ffnh[NTOK * HIDz];
__device__ __nv_bfloat16 g_ffnl[NTOK * HIDz];

__device__ __nv_bfloat16 g_qkvT_hi[Lz * 3 * Cz * Cz];
__device__ __nv_bfloat16 g_qkvT_lo[Lz * 3 * Cz * Cz];
__device__ __nv_bfloat16 g_projT_hi[Lz * Cz * Cz];
__device__ __nv_bfloat16 g_projT_lo[Lz * Cz * Cz];
__device__ __nv_bfloat16 g_fc1T_hi[Lz * HIDz * Cz];
__device__ __nv_bfloat16 g_fc1T_lo[Lz * HIDz * Cz];
__device__ __nv_bfloat16 g_fc2T_hi[Lz * Cz * HIDz];
__device__ __nv_bfloat16 g_fc2T_lo[Lz * Cz * HIDz];
__device__ __nv_bfloat16 g_tok_hi[Vz * Cz];
__device__ __nv_bfloat16 g_tok_lo[Vz * Cz];

// ---------------------------------------------------------------------------
// Weight prep
// ---------------------------------------------------------------------------
__global__ void wtrans_kernel(const float* __restrict__ W,
                              __nv_bfloat16* __restrict__ Th,
                              __nv_bfloat16* __restrict__ Tl,
                              int K, int N) {
    __shared__ float t[32][33];
    const float* Wl = W + (size_t)blockIdx.z * K * N;
    __nv_bfloat16* Thl = Th + (size_t)blockIdx.z * K * N;
    __nv_bfloat16* Tll = Tl + (size_t)blockIdx.z * K * N;
    int n0 = blockIdx.x * 32, k0 = blockIdx.y * 32;
    int tx = threadIdx.x, ty = threadIdx.y;
#pragma unroll
    for (int j = 0; j < 32; j += 8)
        t[ty + j][tx] = Wl[(size_t)(k0 + ty + j) * N + n0 + tx];
    __syncthreads();
#pragma unroll
    for (int j = 0; j < 32; j += 8) {
        float v = t[tx][ty + j];
        __nv_bfloat16 h = __float2bfloat16(v);
        float lo = v - __bfloat162float(h);
        size_t o = (size_t)(n0 + ty + j) * K + k0 + tx;
        Thl[o] = h;
        Tll[o] = __float2bfloat16(lo);
    }
}

__global__ void wsplit_kernel(const float* __restrict__ W,
                              __nv_bfloat16* __restrict__ Th,
                              __nv_bfloat16* __restrict__ Tl, int n) {
    int i = blockIdx.x * blockDim.x + threadIdx.x;
    if (i < n) {
        float v = W[i];
        __nv_bfloat16 h = __float2bfloat16(v);
        Th[i] = h;
        Tl[i] = __float2bfloat16(v - __bfloat162float(h));
    }
}

// ---------------------------------------------------------------------------
// gemm_mma: 128x128 block, 8 warps (64x32 warp tile), BK=32, NSTG=3. (R5)
// ---------------------------------------------------------------------------
#define SPITCH 80
#define S_AH 0
#define S_AL 10240
#define S_BH 20480
#define S_BL 30720
#define S_STG 40960
#define S_GSMEM (3 * S_STG)

__global__ __launch_bounds__(256)
void gemm_mma(const __nv_bfloat16* __restrict__ Ah,
              const __nv_bfloat16* __restrict__ Al,
              const __nv_bfloat16* __restrict__ Bh,
              const __nv_bfloat16* __restrict__ Bl,
              float* __restrict__ Cf,
              __nv_bfloat16* __restrict__ Ch,
              __nv_bfloat16* __restrict__ Cl,
              int M, int N, int K,
              const float* __restrict__ bias, const float* __restrict__ res,
              int gelu) {
    extern __shared__ __align__(128) char smem[];
    uint32_t sb = smem_u32(smem);
    int tid = threadIdx.x, wid = tid >> 5, lane = tid & 31;
    int m0 = blockIdx.y * 128, n0 = blockIdx.x * 128;
    int wm = wid & 1, wn = wid >> 1;

    const __nv_bfloat16* Agh = Ah + (size_t)m0 * K;
    const __nv_bfloat16* Agl = Al + (size_t)m0 * K;
    const __nv_bfloat16* Bgh = Bh + (size_t)n0 * K;
    const __nv_bfloat16* Bgl = Bl + (size_t)n0 * K;

    float acc[4][4][4];
#pragma unroll
    for (int i = 0; i < 4; i++)
#pragma unroll
        for (int j = 0; j < 4; j++)
#pragma unroll
            for (int r = 0; r < 4; r++) acc[i][j][r] = 0.f;

    const int NC = K >> 5;

#define ISSUE_S(c)                                                             \
    {                                                                          \
        uint32_t s0 = sb + ((c) % 3) * S_STG;                                  \
        _Pragma("unroll")                                                      \
        for (int it = 0; it < 2; it++) {                                       \
            int i = it * 256 + tid;                                            \
            int row = i >> 2, seg = i & 3;                                     \
            uint32_t so = row * SPITCH + seg * 16;                             \
            size_t go = (size_t)row * K + (size_t)(c) * 32 + seg * 8;          \
            cp16(s0 + S_AH + so, Agh + go);                                    \
            cp16(s0 + S_AL + so, Agl + go);                                    \
            cp16(s0 + S_BH + so, Bgh + go);                                    \
            cp16(s0 + S_BL + so, Bgl + go);                                    \
        }                                                                      \
        CP_COMMIT();                                                           \
    }

    ISSUE_S(0);
    ISSUE_S(1);

    int r16 = lane & 15, hsel = lane >> 4;
    int bg = lane >> 3;
    int browoff = ((bg & 2) << 2) + (lane & 7);
    int bkoff = (bg & 1) * 8;

    for (int c = 0; c < NC; c++) {
        if (c + 1 < NC) { CP_WAIT1(); } else { CP_WAIT0(); }
        __syncthreads();
        if (c + 2 < NC) ISSUE_S(c + 2);  // writes stage (c-1)%3; all reads done
        uint32_t base = sb + (c % 3) * S_STG;
#pragma unroll
        for (int kk = 0; kk < 32; kk += 16) {
            uint32_t ah[16], al[16], bh[8], bl[8];
#pragma unroll
            for (int mt = 0; mt < 4; mt++) {
                uint32_t ad = (uint32_t)((wm * 64 + mt * 16 + r16) * SPITCH +
                                         (kk + hsel * 8) * 2);
                ldsm_x4(ah + 4 * mt, base + S_AH + ad);
                ldsm_x4(al + 4 * mt, base + S_AL + ad);
            }
#pragma unroll
            for (int ntp = 0; ntp < 2; ntp++) {
                uint32_t bd = (uint32_t)((wn * 32 + ntp * 16 + browoff) * SPITCH +
                                         (kk + bkoff) * 2);
                ldsm_x4(bh + 4 * ntp, base + S_BH + bd);
                ldsm_x4(bl + 4 * ntp, base + S_BL + bd);
            }
#pragma unroll
            for (int mt = 0; mt < 4; mt++)
#pragma unroll
                for (int nt = 0; nt < 4; nt++) {
                    uint32_t* bp  = bh + (nt >> 1) * 4 + (nt & 1) * 2;
                    uint32_t* bp2 = bl + (nt >> 1) * 4 + (nt & 1) * 2;
                    mma16816(acc[mt][nt], ah + 4 * mt, bp);
                    mma16816(acc[mt][nt], ah + 4 * mt, bp2);
                    mma16816(acc[mt][nt], al + 4 * mt, bp);
                }
        }
        __syncthreads();
    }
#undef ISSUE_S

    int gid = lane >> 2, qid = lane & 3;
#pragma unroll
    for (int mt = 0; mt < 4; mt++) {
#pragma unroll
        for (int nt = 0; nt < 4; nt++) {
            int n = n0 + wn * 32 + nt * 8 + 2 * qid;
            float bsum0 = bias ? bias[n] : 0.f;
            float bsum1 = bias ? bias[n + 1] : 0.f;
#pragma unroll
            for (int half = 0; half < 2; half++) {
                int m = m0 + wm * 64 + mt * 16 + gid + half * 8;
                float v0 = acc[mt][nt][half * 2 + 0] + bsum0;
                float v1 = acc[mt][nt][half * 2 + 1] + bsum1;
                if (gelu) {
                    v0 = 0.5f * v0 * (1.f + erff(v0 * 0.70710678118654752f));
                    v1 = 0.5f * v1 * (1.f + erff(v1 * 0.70710678118654752f));
                }
                if (res) {
                    const float* rr = res + (size_t)m * N + n;
                    v0 += rr[0];
                    v1 += rr[1];
                }
                if (Cf) {
                    float2 o;
                    o.x = v0; o.y = v1;
                    *(float2*)(Cf + (size_t)m * N + n) = o;
                }
                if (Ch) {
                    __nv_bfloat162 oh, ol;
                    oh.x = __float2bfloat16(v0);
                    oh.y = __float2bfloat16(v1);
                    ol.x = __float2bfloat16(v0 - __bfloat162float(oh.x));
                    ol.y = __float2bfloat16(v1 - __bfloat162float(oh.y));
                    *(__nv_bfloat162*)(Ch + (size_t)m * N + n) = oh;
                    *(__nv_bfloat162*)(Cl + (size_t)m * N + n) = ol;
                }
            }
        }
    }
}

// ---------------------------------------------------------------------------
// gemm_big: 128x256 block, 8 warps (64x64 warp tile), BK=32, NSTG=3.
// For N >= 2048 GEMMs (qkv, fc1, lm_head). 2 warps/SMSP retained.
// ---------------------------------------------------------------------------
#define B_AH 0
#define B_AL 10240
#define B_BH 20480
#define B_BL 40960
#define B_STG 61440
#define B_GSMEM (3 * B_STG)     // 184320

__global__ __launch_bounds__(256)
void gemm_big(const __nv_bfloat16* __restrict__ Ah,
              const __nv_bfloat16* __restrict__ Al,
              const __nv_bfloat16* __restrict__ Bh,
              const __nv_bfloat16* __restrict__ Bl,
              float* __restrict__ Cf,
              __nv_bfloat16* __restrict__ Ch,
              __nv_bfloat16* __restrict__ Cl,
              int M, int N, int K,
              const float* __restrict__ bias, const float* __restrict__ res,
              int gelu) {
    extern __shared__ __align__(128) char smem[];
    uint32_t sb = smem_u32(smem);
    int tid = threadIdx.x, wid = tid >> 5, lane = tid & 31;
    int m0 = blockIdx.y * 128, n0 = blockIdx.x * 256;
    int wm = wid & 1, wn = wid >> 1;           // wn 0..3 over 256 n

    const __nv_bfloat16* Agh = Ah + (size_t)m0 * K;
    const __nv_bfloat16* Agl = Al + (size_t)m0 * K;
    const __nv_bfloat16* Bgh = Bh + (size_t)n0 * K;
    const __nv_bfloat16* Bgl = Bl + (size_t)n0 * K;

    float acc[4][8][4];
#pragma unroll
    for (int i = 0; i < 4; i++)
#pragma unroll
        for (int j = 0; j < 8; j++)
#pragma unroll
            for (int r = 0; r < 4; r++) acc[i][j][r] = 0.f;

    const int NC = K >> 5;

#define ISSUE_B(c)                                                             \
    {                                                                          \
        uint32_t s0 = sb + ((c) % 3) * B_STG;                                  \
        _Pragma("unroll")                                                      \
        for (int it = 0; it < 2; it++) {                                       \
            int i = it * 256 + tid;                                            \
            int row = i >> 2, seg = i & 3;                                     \
            uint32_t so = row * SPITCH + seg * 16;                             \
            size_t go = (size_t)row * K + (size_t)(c) * 32 + seg * 8;          \
            cp16(s0 + B_AH + so, Agh + go);                                    \
            cp16(s0 + B_AL + so, Agl + go);                                    \
        }                                                                      \
        _Pragma("unroll")                                                      \
        for (int it = 0; it < 4; it++) {                                       \
            int i = it * 256 + tid;                                            \
            int row = i >> 2, seg = i & 3;                                     \
            uint32_t so = row * SPITCH + seg * 16;                             \
            size_t go = (size_t)row * K + (size_t)(c) * 32 + seg * 8;          \
            cp16(s0 + B_BH + so, Bgh + go);                                    \
            cp16(s0 + B_BL + so, Bgl + go);                                    \
        }                                                                      \
        CP_COMMIT();                                                           \
    }

    ISSUE_B(0);
    ISSUE_B(1);

    int r16 = lane & 15, hsel = lane >> 4;
    int bg = lane >> 3;
    int browoff = ((bg & 2) << 2) + (lane & 7);
    int bkoff = (bg & 1) * 8;

    for (int c = 0; c < NC; c++) {
        if (c + 1 < NC) { CP_WAIT1(); } else { CP_WAIT0(); }
        __syncthreads();
        if (c + 2 < NC) ISSUE_B(c + 2);
        uint32_t base = sb + (c % 3) * B_STG;
#pragma unroll
        for (int kk = 0; kk < 32; kk += 16) {
            uint32_t ah[16], al[16], bh[16], bl[16];
#pragma unroll
            for (int mt = 0; mt < 4; mt++) {
                uint32_t ad = (uint32_t)((wm * 64 + mt * 16 + r16) * SPITCH +
                                         (kk + hsel * 8) * 2);
                ldsm_x4(ah + 4 * mt, base + B_AH + ad);
                ldsm_x4(al + 4 * mt, base + B_AL + ad);
            }
#pragma unroll
            for (int np = 0; np < 4; np++) {
                uint32_t bd = (uint32_t)((wn * 64 + np * 16 + browoff) * SPITCH +
                                         (kk + bkoff) * 2);
                ldsm_x4(bh + 4 * np, base + B_BH + bd);
                ldsm_x4(bl + 4 * np, base + B_BL + bd);
            }
#pragma unroll
            for (int mt = 0; mt < 4; mt++)
#pragma unroll
                for (int nt = 0; nt < 8; nt++) {
                    uint32_t* bp  = bh + (nt >> 1) * 4 + (nt & 1) * 2;
                    uint32_t* bp2 = bl + (nt >> 1) * 4 + (nt & 1) * 2;
                    mma16816(acc[mt][nt], ah + 4 * mt, bp);
                    mma16816(acc[mt][nt], ah + 4 * mt, bp2);
                    mma16816(acc[mt][nt], al + 4 * mt, bp);
                }
        }
        __syncthreads();
    }
#undef ISSUE_B

    int gid = lane >> 2, qid = lane & 3;
#pragma unroll
    for (int mt = 0; mt < 4; mt++) {
#pragma unroll
        for (int nt = 0; nt < 8; nt++) {
            int n = n0 + wn * 64 + nt * 8 + 2 * qid;
            float bsum0 = bias ? bias[n] : 0.f;
            float bsum1 = bias ? bias[n + 1] : 0.f;
#pragma unroll
            for (int half = 0; half < 2; half++) {
                int m = m0 + wm * 64 + mt * 16 + gid + half * 8;
                float v0 = acc[mt][nt][half * 2 + 0] + bsum0;
                float v1 = acc[mt][nt][half * 2 + 1] + bsum1;
                if (gelu) {
                    v0 = 0.5f * v0 * (1.f + erff(v0 * 0.70710678118654752f));
                    v1 = 0.5f * v1 * (1.f + erff(v1 * 0.70710678118654752f));
                }
                if (res) {
                    const float* rr = res + (size_t)m * N + n;
                    v0 += rr[0];
                    v1 += rr[1];
                }
                if (Cf) {
                    float2 o;
                    o.x = v0; o.y = v1;
                    *(float2*)(Cf + (size_t)m * N + n) = o;
                }
                if (Ch) {
                    __nv_bfloat162 oh, ol;
                    oh.x = __float2bfloat16(v0);
                    oh.y = __float2bfloat16(v1);
                    ol.x = __float2bfloat16(v0 - __bfloat162float(oh.x));
                    ol.y = __float2bfloat16(v1 - __bfloat162float(oh.y));
                    *(__nv_bfloat162*)(Ch + (size_t)m * N + n) = oh;
                    *(__nv_bfloat162*)(Cl + (size_t)m * N + n) = ol;
                }
            }
        }
    }
}

// ---------------------------------------------------------------------------
// MMA flash attention (unchanged from R5)
// ---------------------------------------------------------------------------
#define APITCH  144
#define AT_TILE 9216
#define AT_Q    0
#define AT_KV0  (2 * AT_TILE)
#define AT_KVS  (4 * AT_TILE)
#define AT_SMEM (AT_KV0 + 2 * AT_KVS)

__global__ __launch_bounds__(128)
void attn_mma(const __nv_bfloat16* __restrict__ qkvh,
              const __nv_bfloat16* __restrict__ qkvl,
              __nv_bfloat16* __restrict__ oh,
              __nv_bfloat16* __restrict__ ol) {
    extern __shared__ __align__(128) char smem[];
    uint32_t sb = smem_u32(smem);
    int tid = threadIdx.x, w = tid >> 5, lane = tid & 31;
    int qi = (int)gridDim.x - 1 - (int)blockIdx.x;
    int bh = blockIdx.y;
    int b = bh >> 4, h = bh & 15;
    const int RS = 3 * Cz;
    const size_t tokbase = (size_t)(b * Tz) * RS + h * Dz;

    int gid = lane >> 2, qid = lane & 3;
    int r16 = lane & 15, hsel = lane >> 4;
    int bg = lane >> 3;
    int browoff = ((bg & 2) << 2) + (lane & 7);
    int bkoff = (bg & 1) * 8;
    int t_row = (bg & 1) * 8 + (lane & 7);
    int t_col = (bg >> 1) * 8;

#define ISSUE_KV(kt)                                                           \
    {                                                                          \
        uint32_t s0 = sb + AT_KV0 + ((kt) & 1) * AT_KVS;                       \
        const __nv_bfloat16* srcs[4] = {                                       \
            qkvh + tokbase + Cz, qkvl + tokbase + Cz,                          \
            qkvh + tokbase + 2 * Cz, qkvl + tokbase + 2 * Cz };                \
        _Pragma("unroll")                                                      \
        for (int t = 0; t < 4; t++) {                                          \
            _Pragma("unroll")                                                  \
            for (int it = 0; it < 4; it++) {                                   \
                int i = it * 128 + tid;                                        \
                int r = i >> 3, s = i & 7;                                     \
                cp16(s0 + t * AT_TILE + r * APITCH + s * 16,                   \
                     srcs[t] + (size_t)((kt) * 64 + r) * RS + s * 8);          \
            }                                                                  \
        }                                                                      \
        CP_COMMIT();                                                           \
    }

    {
#pragma unroll
        for (int t = 0; t < 2; t++) {
            const __nv_bfloat16* src = (t ? qkvl : qkvh) + tokbase;
            uint32_t dst = sb + AT_Q + t * AT_TILE;
#pragma unroll
            for (int it = 0; it < 4; it++) {
                int i = it * 128 + tid;
                int r = i >> 3, s = i & 7;
                cp16(dst + r * APITCH + s * 16,
                     src + (size_t)(qi * 64 + r) * RS + s * 8);
            }
        }
        uint32_t s0 = sb + AT_KV0;
        const __nv_bfloat16* srcs[4] = {
            qkvh + tokbase + Cz, qkvl + tokbase + Cz,
            qkvh + tokbase + 2 * Cz, qkvl + tokbase + 2 * Cz };
#pragma unroll
        for (int t = 0; t < 4; t++) {
#pragma unroll
            for (int it = 0; it < 4; it++) {
                int i = it * 128 + tid;
                int r = i >> 3, s = i & 7;
                cp16(s0 + t * AT_TILE + r * APITCH + s * 16,
                     srcs[t] + (size_t)r * RS + s * 8);
            }
        }
        CP_COMMIT();
    }
    if (qi >= 1) ISSUE_KV(1);

    if (qi >= 1) { CP_WAIT1(); } else { CP_WAIT0(); }
    __syncthreads();

    uint32_t qfh[4][4], qfl[4][4];
#pragma unroll
    for (int kk = 0; kk < 4; kk++) {
        uint32_t ad = sb + AT_Q + (uint32_t)((w * 16 + r16) * APITCH +
                                             (kk * 16 + hsel * 8) * 2);
        ldsm_x4(qfh[kk], ad);
        ldsm_x4(qfl[kk], ad + AT_TILE);
    }

    float oacc[8][4];
#pragma unroll
    for (int i = 0; i < 8; i++)
#pragma unroll
        for (int j = 0; j < 4; j++) oacc[i][j] = 0.f;
    float mrow[2] = {-1e30f, -1e30f};
    float lrow[2] = {0.f, 0.f};

    for (int kt = 0; kt <= qi; kt++) {
        if (kt > 0) {
            if (kt < qi) { CP_WAIT1(); } else { CP_WAIT0(); }
            __syncthreads();
        }
        uint32_t kb = sb + AT_KV0 + (kt & 1) * AT_KVS;

        float s[8][4];
#pragma unroll
        for (int i = 0; i < 8; i++)
#pragma unroll
            for (int j = 0; j < 4; j++) s[i][j] = 0.f;
#pragma unroll
        for (int kk = 0; kk < 4; kk++) {
            uint32_t kh[16], kl[16];
#pragma unroll
            for (int np = 0; np < 4; np++) {
                uint32_t ad = kb + (uint32_t)((np * 16 + browoff) * APITCH +
                                              (kk * 16 + bkoff) * 2);
                ldsm_x4(kh + 4 * np, ad);
                ldsm_x4(kl + 4 * np, ad + AT_TILE);
            }
#pragma unroll
            for (int nt = 0; nt < 8; nt++) {
                uint32_t* bp = kh + (nt >> 1) * 4 + (nt & 1) * 2;
                uint32_t* bl2 = kl + (nt >> 1) * 4 + (nt & 1) * 2;
                mma16816(s[nt], qfh[kk], bp);
                mma16816(s[nt], qfh[kk], bl2);
                mma16816(s[nt], qfl[kk], bp);
            }
        }
#pragma unroll
        for (int nt = 0; nt < 8; nt++)
#pragma unroll
            for (int j = 0; j < 4; j++) s[nt][j] *= 0.125f;
        if (kt == qi) {
#pragma unroll
            for (int nt = 0; nt < 8; nt++)
#pragma unroll
                for (int j = 0; j < 4; j++) {
                    int kc = 8 * nt + 2 * qid + (j & 1);
                    int qr = w * 16 + gid + (j >> 1) * 8;
                    if (kc > qr) s[nt][j] = -1e30f;
                }
        }
        float mt0 = -1e30f, mt1 = -1e30f;
#pragma unroll
        for (int nt = 0; nt < 8; nt++) {
            mt0 = fmaxf(mt0, fmaxf(s[nt][0], s[nt][1]));
            mt1 = fmaxf(mt1, fmaxf(s[nt][2], s[nt][3]));
        }
        mt0 = fmaxf(mt0, __shfl_xor_sync(0xffffffffu, mt0, 1));
        mt0 = fmaxf(mt0, __shfl_xor_sync(0xffffffffu, mt0, 2));
        mt1 = fmaxf(mt1, __shfl_xor_sync(0xffffffffu, mt1, 1));
        mt1 = fmaxf(mt1, __shfl_xor_sync(0xffffffffu, mt1, 2));
        float mn0 = fmaxf(mrow[0], mt0), mn1 = fmaxf(mrow[1], mt1);
        float c0 = __expf(mrow[0] - mn0), c1 = __expf(mrow[1] - mn1);
        mrow[0] = mn0; mrow[1] = mn1;
        float rs0 = 0.f, rs1 = 0.f;
#pragma unroll
        for (int nt = 0; nt < 8; nt++) {
            s[nt][0] = __expf(s[nt][0] - mn0);
            s[nt][1] = __expf(s[nt][1] - mn0);
            s[nt][2] = __expf(s[nt][2] - mn1);
            s[nt][3] = __expf(s[nt][3] - mn1);
            rs0 += s[nt][0] + s[nt][1];
            rs1 += s[nt][2] + s[nt][3];
        }
        rs0 += __shfl_xor_sync(0xffffffffu, rs0, 1);
        rs0 += __shfl_xor_sync(0xffffffffu, rs0, 2);
        rs1 += __shfl_xor_sync(0xffffffffu, rs1, 1);
        rs1 += __shfl_xor_sync(0xffffffffu, rs1, 2);
        lrow[0] = lrow[0] * c0 + rs0;
        lrow[1] = lrow[1] * c1 + rs1;
#pragma unroll
        for (int nt = 0; nt < 8; nt++) {
            oacc[nt][0] *= c0; oacc[nt][1] *= c0;
            oacc[nt][2] *= c1; oacc[nt][3] *= c1;
        }
#pragma unroll
        for (int k2 = 0; k2 < 4; k2++) {
            uint32_t pah[4], pal[4];
            {
                float p00 = s[2 * k2][0],     p01 = s[2 * k2][1];
                float p10 = s[2 * k2][2],     p11 = s[2 * k2][3];
                float p20 = s[2 * k2 + 1][0], p21 = s[2 * k2 + 1][1];
                float p30 = s[2 * k2 + 1][2], p31 = s[2 * k2 + 1][3];
                pah[0] = packbf(p00, p01);
                pah[1] = packbf(p10, p11);
                pah[2] = packbf(p20, p21);
                pah[3] = packbf(p30, p31);
                __nv_bfloat162* hp;
                hp = (__nv_bfloat162*)&pah[0];
                pal[0] = packbf(p00 - __bfloat162float(hp->x), p01 - __bfloat162float(hp->y));
                hp = (__nv_bfloat162*)&pah[1];
                pal[1] = packbf(p10 - __bfloat162float(hp->x), p11 - __bfloat162float(hp->y));
                hp = (__nv_bfloat162*)&pah[2];
                pal[2] = packbf(p20 - __bfloat162float(hp->x), p21 - __bfloat162float(hp->y));
                hp = (__nv_bfloat162*)&pah[3];
                pal[3] = packbf(p30 - __bfloat162float(hp->x), p31 - __bfloat162float(hp->y));
            }
            uint32_t vh[16], vl[16];
#pragma unroll
            for (int np = 0; np < 4; np++) {
                uint32_t ad = kb + 2 * AT_TILE +
                              (uint32_t)((k2 * 16 + t_row) * APITCH +
                                         (np * 16 + t_col) * 2);
                ldsm_x4t(vh + 4 * np, ad);
                ldsm_x4t(vl + 4 * np, ad + AT_TILE);
            }
#pragma unroll
            for (int nt = 0; nt < 8; nt++) {
                uint32_t* bp = vh + (nt >> 1) * 4 + (nt & 1) * 2;
                uint32_t* bl2 = vl + (nt >> 1) * 4 + (nt & 1) * 2;
                mma16816(oacc[nt], pah, bp);
                mma16816(oacc[nt], pah, bl2);
                mma16816(oacc[nt], pal, bp);
            }
        }
        __syncthreads();
        if (kt + 2 <= qi) ISSUE_KV(kt + 2);
    }
#undef ISSUE_KV

    float inv0 = 1.f / lrow[0], inv1 = 1.f / lrow[1];
    int tok0 = b * Tz + qi * 64 + w * 16 + gid;
#pragma unroll
    for (int nt = 0; nt < 8; nt++) {
        int col = h * Dz + 8 * nt + 2 * qid;
        float v0 = oacc[nt][0] * inv0, v1 = oacc[nt][1] * inv0;
        float v2 = oacc[nt][2] * inv1, v3 = oacc[nt][3] * inv1;
        __nv_bfloat162 ph, pl;
        ph.x = __float2bfloat16(v0); ph.y = __float2bfloat16(v1);
        pl.x = __float2bfloat16(v0 - __bfloat162float(ph.x));
        pl.y = __float2bfloat16(v1 - __bfloat162float(ph.y));
        *(__nv_bfloat162*)(oh + (size_t)tok0 * Cz + col) = ph;
        *(__nv_bfloat162*)(ol + (size_t)tok0 * Cz + col) = pl;
        ph.x = __float2bfloat16(v2); ph.y = __float2bfloat16(v3);
        pl.x = __float2bfloat16(v2 - __bfloat162float(ph.x));
        pl.y = __float2bfloat16(v3 - __bfloat162float(ph.y));
        *(__nv_bfloat162*)(oh + (size_t)(tok0 + 8) * Cz + col) = ph;
        *(__nv_bfloat162*)(ol + (size_t)(tok0 + 8) * Cz + col) = pl;
    }
}

// ---------------------------------------------------------------------------
// Embedding
// ---------------------------------------------------------------------------
__global__ void embed_kernel(const int* __restrict__ idx,
                             const float* __restrict__ tok,
                             const float* __restrict__ pos,
                             float* __restrict__ x) {
    int row = blockIdx.x;
    int t   = row & (Tz - 1);
    int tokid = idx[row];
    const float* te = tok + (size_t)tokid * Cz;
    const float* pe = pos + (size_t)t * Cz;
    float* xr = x + (size_t)row * Cz;
    for (int i = threadIdx.x; i < Cz; i += blockDim.x)
        xr[i] = te[i] + pe[i];
}

// ---------------------------------------------------------------------------
// LayerNorm per row, writes bf16 hi/lo split
// ---------------------------------------------------------------------------
__global__ void ln_kernel(const float* __restrict__ x,
                          __nv_bfloat16* __restrict__ yh,
                          __nv_bfloat16* __restrict__ yl,
                          const float* __restrict__ g, const float* __restrict__ b) {
    int row = blockIdx.x;
    const float* xr = x + (size_t)row * Cz;
    float s = 0.f, s2 = 0.f;
    for (int i = threadIdx.x; i < Cz; i += blockDim.x) {
        float v = xr[i];
        s += v; s2 += v * v;
    }
    __shared__ float sh_s[8], sh_s2[8];
    for (int off = 16; off > 0; off >>= 1) {
        s  += __shfl_down_sync(0xffffffffu, s,  off);
        s2 += __shfl_down_sync(0xffffffffu, s2, off);
    }
    int lane = threadIdx.x & 31, wid = threadIdx.x >> 5;
    if (lane == 0) { sh_s[wid] = s; sh_s2[wid] = s2; }
    __syncthreads();
    if (wid == 0) {
        s  = (lane < 8) ? sh_s[lane]  : 0.f;
        s2 = (lane < 8) ? sh_s2[lane] : 0.f;
        for (int off = 4; off > 0; off >>= 1) {
            s  += __shfl_down_sync(0xffffffffu, s,  off);
            s2 += __shfl_down_sync(0xffffffffu, s2, off);
        }
        if (lane == 0) { sh_s[0] = s; sh_s2[0] = s2; }
    }
    __syncthreads();
    float mean = sh_s[0] * (1.f / Cz);
    float var  = sh_s2[0] * (1.f / Cz) - mean * mean;
    float rstd = rsqrtf(var + EPSz);
    __nv_bfloat16* yhr = yh + (size_t)row * Cz;
    __nv_bfloat16* ylr = yl + (size_t)row * Cz;
    for (int i = threadIdx.x; i < Cz; i += blockDim.x) {
        float v = (xr[i] - mean) * rstd * g[i] + b[i];
        __nv_bfloat16 h = __float2bfloat16(v);
        yhr[i] = h;
        ylr[i] = __float2bfloat16(v - __bfloat162float(h));
    }
}

// ---------------------------------------------------------------------------
// Launch
// ---------------------------------------------------------------------------
extern "C" void kernel_launch(void* const* d_in, const int* in_sizes, int n_in,
                              void* d_out, int out_size) {
    const int*   idx     = (const int*)  d_in[0];
    const float* tok_emb = (const float*)d_in[1];
    const float* pos_emb = (const float*)d_in[2];
    const float* qkv_w   = (const float*)d_in[3];
    const float* proj_w  = (const float*)d_in[4];
    const float* proj_b  = (const float*)d_in[5];
    const float* ln1_g   = (const float*)d_in[6];
    const float* ln1_b   = (const float*)d_in[7];
    const float* ln2_g   = (const float*)d_in[8];
    const float* ln2_b   = (const float*)d_in[9];
    const float* fc1_w   = (const float*)d_in[10];
    const float* fc1_b   = (const float*)d_in[11];
    const float* fc2_w   = (const float*)d_in[12];
    const float* fc2_b   = (const float*)d_in[13];
    const float* lnf_g   = (const float*)d_in[14];
    const float* lnf_b   = (const float*)d_in[15];
    float* out = (float*)d_out;

    float* x;
    cudaGetSymbolAddress((void**)&x, g_x);
    __nv_bfloat16 *hh, *hl, *qkvh, *qkvl, *atth, *attl, *ffnh, *ffnl;
    cudaGetSymbolAddress((void**)&hh,   g_hh);
    cudaGetSymbolAddress((void**)&hl,   g_hl);
    cudaGetSymbolAddress((void**)&qkvh, g_qkvh);
    cudaGetSymbolAddress((void**)&qkvl, g_qkvl);
    cudaGetSymbolAddress((void**)&atth, g_atth);
    cudaGetSymbolAddress((void**)&attl, g_attl);
    cudaGetSymbolAddress((void**)&ffnh, g_ffnh);
    cudaGetSymbolAddress((void**)&ffnl, g_ffnl);
    __nv_bfloat16 *qkvTh, *qkvTl, *projTh, *projTl, *fc1Th, *fc1Tl, *fc2Th, *fc2Tl, *tokh, *tokl;
    cudaGetSymbolAddress((void**)&qkvTh, g_qkvT_hi);
    cudaGetSymbolAddress((void**)&qkvTl, g_qkvT_lo);
    cudaGetSymbolAddress((void**)&projTh, g_projT_hi);
    cudaGetSymbolAddress((void**)&projTl, g_projT_lo);
    cudaGetSymbolAddress((void**)&fc1Th, g_fc1T_hi);
    cudaGetSymbolAddress((void**)&fc1Tl, g_fc1T_lo);
    cudaGetSymbolAddress((void**)&fc2Th, g_fc2T_hi);
    cudaGetSymbolAddress((void**)&fc2Tl, g_fc2T_lo);
    cudaGetSymbolAddress((void**)&tokh, g_tok_hi);
    cudaGetSymbolAddress((void**)&tokl, g_tok_lo);

    cudaFuncSetAttribute(gemm_mma, cudaFuncAttributeMaxDynamicSharedMemorySize, S_GSMEM);
    cudaFuncSetAttribute(gemm_big, cudaFuncAttributeMaxDynamicSharedMemorySize, B_GSMEM);
    cudaFuncSetAttribute(attn_mma, cudaFuncAttributeMaxDynamicSharedMemorySize, AT_SMEM);

    // ---- weight prep ----
    dim3 tb(32, 8);
    wtrans_kernel<<<dim3(3 * Cz / 32, Cz / 32, Lz), tb>>>(qkv_w, qkvTh, qkvTl, Cz, 3 * Cz);
    wtrans_kernel<<<dim3(Cz / 32, Cz / 32, Lz), tb>>>(proj_w, projTh, projTl, Cz, Cz);
    wtrans_kernel<<<dim3(HIDz / 32, Cz / 32, Lz), tb>>>(fc1_w, fc1Th, fc1Tl, Cz, HIDz);
    wtrans_kernel<<<dim3(Cz / 32, HIDz / 32, Lz), tb>>>(fc2_w, fc2Th, fc2Tl, HIDz, Cz);
    wsplit_kernel<<<(Vz * Cz + 255) / 256, 256>>>(tok_emb, tokh, tokl, Vz * Cz);

    embed_kernel<<<NTOK, 256>>>(idx, tok_emb, pos_emb, x);

    for (int l = 0; l < Lz; l++) {
        const __nv_bfloat16* qwh = qkvTh + (size_t)l * 3 * Cz * Cz;
        const __nv_bfloat16* qwl = qkvTl + (size_t)l * 3 * Cz * Cz;
        const __nv_bfloat16* pwh = projTh + (size_t)l * Cz * Cz;
        const __nv_bfloat16* pwl = projTl + (size_t)l * Cz * Cz;
        const __nv_bfloat16* w1h = fc1Th + (size_t)l * Cz * HIDz;
        const __nv_bfloat16* w1l = fc1Tl + (size_t)l * Cz * HIDz;
        const __nv_bfloat16* w2h = fc2Th + (size_t)l * Cz * HIDz;
        const __nv_bfloat16* w2l = fc2Tl + (size_t)l * Cz * HIDz;
        const float* pb  = proj_b + (size_t)l * Cz;
        const float* b1  = fc1_b  + (size_t)l * HIDz;
        const float* b2  = fc2_b  + (size_t)l * Cz;

        ln_kernel<<<NTOK, 256>>>(x, hh, hl, ln1_g + l * Cz, ln1_b + l * Cz);
        gemm_big<<<dim3(3 * Cz / 256, NTOK / 128), 256, B_GSMEM>>>(
            hh, hl, qwh, qwl, nullptr, qkvh, qkvl,
            NTOK, 3 * Cz, Cz, nullptr, nullptr, 0);
        attn_mma<<<dim3(Tz / 64, Bz * Hz), 128, AT_SMEM>>>(qkvh, qkvl, atth, attl);
        gemm_mma<<<dim3(Cz / 128, NTOK / 128), 256, S_GSMEM>>>(
            atth, attl, pwh, pwl, x, nullptr, nullptr,
            NTOK, Cz, Cz, pb, x, 0);
        ln_kernel<<<NTOK, 256>>>(x, hh, hl, ln2_g + l * Cz, ln2_b + l * Cz);
        gemm_big<<<dim3(HIDz / 256, NTOK / 128), 256, B_GSMEM>>>(
            hh, hl, w1h, w1l, nullptr, ffnh, ffnl,
            NTOK, HIDz, Cz, b1, nullptr, 1);
        gemm_mma<<<dim3(Cz / 128, NTOK / 128), 256, S_GSMEM>>>(
            ffnh, ffnl, w2h, w2l, x, nullptr, nullptr,
            NTOK, Cz, HIDz, b2, x, 0);
    }

    ln_kernel<<<NTOK, 256>>>(x, hh, hl, lnf_g, lnf_b);
    gemm_big<<<dim3(Vz / 256, NTOK / 128), 256, B_GSMEM>>>(
        hh, hl, tokh, tokl, out, nullptr, nullptr,
        NTOK, Vz, Cz, nullptr, nullptr, 0);
}